// round 1
// baseline (speedup 1.0000x reference)
#include <cuda_runtime.h>

#define BB 8
#define NSEQ 4096
#define DIM 256
#define HEADS 8
#define HD 32
#define NBIN 17
#define MROWS (BB * NSEQ)        // 32768
#define BHN (BB * HEADS)         // 64
#define NXF (BHN * NBIN * NSEQ)  // 4456448 complex per array

// ---------------- scratch (static device memory; no allocations) ----------------
__device__ float  g_QL[MROWS * DIM];
__device__ float  g_KL[MROWS * DIM];
__device__ float  g_VL[MROWS * DIM];
__device__ float2 g_XF[2 * NXF];   // [0]=Qhat bins, [1]=Khat bins (freq along seq, bitrev order after fwd FFT)
__device__ float2 g_Z[NXF];        // seq-domain, head-freq-domain conv result

__device__ __forceinline__ float2 cmulf(float2 a, float2 b) {
    return make_float2(fmaf(a.x, b.x, -a.y * b.y), fmaf(a.x, b.y, a.y * b.x));
}

// ---------------- Kernel 1: fused 3-way projection GEMM ----------------
// O[m,c] = sum_k X[m,k] * W[c,k] + bias[c]    (X @ W.T + b), fp32.
struct GemmArgs {
    const float* X[3];
    const float* W[3];
    const float* bias[3];
};

__global__ __launch_bounds__(256, 2) void proj_gemm(GemmArgs args) {
    __shared__ float As[32][128];
    __shared__ float Bs[32][128];
    const int z = blockIdx.z;
    const float* __restrict__ A    = args.X[z];
    const float* __restrict__ W    = args.W[z];
    const float* __restrict__ bias = args.bias[z];
    float* __restrict__ O = (z == 0) ? g_QL : (z == 1) ? g_KL : g_VL;

    const int bm = blockIdx.x * 128;
    const int bn = blockIdx.y * 128;
    const int tid = threadIdx.x;
    const int tx = tid & 15;
    const int ty = tid >> 4;

    float acc[8][8];
#pragma unroll
    for (int i = 0; i < 8; i++)
#pragma unroll
        for (int j = 0; j < 8; j++) acc[i][j] = 0.f;

    for (int k0 = 0; k0 < DIM; k0 += 32) {
#pragma unroll
        for (int i = 0; i < 4; i++) {
            int idx = tid + i * 256;       // 0..1023
            int r   = idx >> 3;            // 0..127
            int c   = (idx & 7) << 2;      // 0,4,...,28
            float4 va = *(const float4*)(A + (bm + r) * DIM + k0 + c);
            As[c + 0][r] = va.x; As[c + 1][r] = va.y; As[c + 2][r] = va.z; As[c + 3][r] = va.w;
            float4 vb = *(const float4*)(W + (bn + r) * DIM + k0 + c);
            Bs[c + 0][r] = vb.x; Bs[c + 1][r] = vb.y; Bs[c + 2][r] = vb.z; Bs[c + 3][r] = vb.w;
        }
        __syncthreads();
#pragma unroll
        for (int k = 0; k < 32; k++) {
            float a[8], b[8];
            *(float4*)&a[0] = *(const float4*)&As[k][ty << 3];
            *(float4*)&a[4] = *(const float4*)&As[k][(ty << 3) + 4];
            *(float4*)&b[0] = *(const float4*)&Bs[k][tx << 3];
            *(float4*)&b[4] = *(const float4*)&Bs[k][(tx << 3) + 4];
#pragma unroll
            for (int i = 0; i < 8; i++)
#pragma unroll
                for (int j = 0; j < 8; j++)
                    acc[i][j] = fmaf(a[i], b[j], acc[i][j]);
        }
        __syncthreads();
    }
#pragma unroll
    for (int i = 0; i < 8; i++) {
        int row = bm + (ty << 3) + i;
#pragma unroll
        for (int j = 0; j < 8; j++) {
            int col = bn + (tx << 3) + j;
            O[row * DIM + col] = acc[i][j] + bias[col];
        }
    }
}

// ---------------- Kernel 2: rfft along head_dim (32 -> 17 bins) ----------------
// Output layout: XF[(bh*17+j)*4096 + n], natural seq order. blockIdx.y: 0=Q, 1=K.
__global__ __launch_bounds__(128) void rfft_d_kernel() {
    __shared__ float xs[128][33];
    __shared__ float ct[32], st[32];
    const int y = blockIdx.y;
    const float* __restrict__ src = y ? g_KL : g_QL;
    float2* __restrict__ dst = g_XF + (size_t)y * NXF;

    const int bx = blockIdx.x;
    const int bh = bx >> 5;            // 0..63
    const int chunk = bx & 31;
    const int b = bh >> 3, h = bh & 7;
    const int n0 = chunk * 128;
    const int tid = threadIdx.x;

    if (tid < 32) {
        float s, c;
        sincospif((float)tid / 16.0f, &s, &c);  // angle = 2*pi*tid/32
        ct[tid] = c; st[tid] = s;
    }
    const int rowbase = (b * NSEQ + n0) * DIM + h * HD;
#pragma unroll
    for (int i = 0; i < 8; i++) {
        int idx = i * 128 + tid;       // 0..1023 float4s
        int r = idx >> 3;              // row 0..127
        int c = (idx & 7) << 2;        // 0..28
        float4 v = *(const float4*)(src + rowbase + r * DIM + c);
        xs[r][c + 0] = v.x; xs[r][c + 1] = v.y; xs[r][c + 2] = v.z; xs[r][c + 3] = v.w;
    }
    __syncthreads();

    float x[32];
#pragma unroll
    for (int d = 0; d < 32; d++) x[d] = xs[tid][d];

    const int n = n0 + tid;
    for (int j = 0; j <= 16; j++) {
        float re = 0.f, im = 0.f;
        int k = 0;
#pragma unroll
        for (int d = 0; d < 32; d++) {
            re = fmaf(x[d], ct[k], re);
            im = fmaf(-x[d], st[k], im);
            k = (k + j) & 31;
        }
        dst[((bh * NBIN + j) << 12) + n] = make_float2(re, im);
    }
}

// ---------------- Kernel 3a: forward 4096-pt FFT (DIF, natural -> bitrev), in place ----------------
__global__ __launch_bounds__(512) void fft_fwd_kernel() {
    __shared__ float2 buf[4096];
    __shared__ float2 tw[2048];   // tw[k] = exp(-i*pi*k/2048)
    const int tid = threadIdx.x;
    float2* __restrict__ col = g_XF + ((size_t)blockIdx.x << 12);

    for (int k = tid; k < 2048; k += 512) {
        float s, c;
        sincospif((float)k / 2048.0f, &s, &c);
        tw[k] = make_float2(c, -s);
    }
    for (int i = tid; i < 4096; i += 512) buf[i] = col[i];
    __syncthreads();

    for (int sh = 11; sh >= 0; sh--) {       // half = 2048 .. 1
        const int h = 1 << sh;
#pragma unroll
        for (int r = 0; r < 4; r++) {
            int t = tid + (r << 9);
            int pos = t & (h - 1);
            int i0 = ((t >> sh) << (sh + 1)) | pos;
            int i1 = i0 + h;
            float2 a = buf[i0], bb = buf[i1];
            float2 w = tw[pos << (11 - sh)];
            buf[i0] = make_float2(a.x + bb.x, a.y + bb.y);
            float2 d = make_float2(a.x - bb.x, a.y - bb.y);
            buf[i1] = cmulf(d, w);
        }
        __syncthreads();
    }
    for (int i = tid; i < 4096; i += 512) col[i] = buf[i];
}

// ---------------- Kernel 3b: pointwise product (bitrev domain) + inverse FFT (DIT) ----------------
__global__ __launch_bounds__(512) void fft_inv_kernel() {
    __shared__ float2 buf[4096];
    __shared__ float2 tw[2048];   // tw[k] = exp(+i*pi*k/2048)
    const int tid = threadIdx.x;
    const float2* __restrict__ qc = g_XF + ((size_t)blockIdx.x << 12);
    const float2* __restrict__ kc = g_XF + (size_t)NXF + ((size_t)blockIdx.x << 12);
    float2* __restrict__ out = g_Z + ((size_t)blockIdx.x << 12);

    for (int k = tid; k < 2048; k += 512) {
        float s, c;
        sincospif((float)k / 2048.0f, &s, &c);
        tw[k] = make_float2(c, s);
    }
    const float inv = 1.0f / 4096.0f;
    for (int i = tid; i < 4096; i += 512) {
        float2 p = cmulf(qc[i], kc[i]);
        buf[i] = make_float2(p.x * inv, p.y * inv);
    }
    __syncthreads();

    for (int sh = 0; sh <= 11; sh++) {       // half = 1 .. 2048
        const int h = 1 << sh;
#pragma unroll
        for (int r = 0; r < 4; r++) {
            int t = tid + (r << 9);
            int pos = t & (h - 1);
            int i0 = ((t >> sh) << (sh + 1)) | pos;
            int i1 = i0 + h;
            float2 a = buf[i0], bb = buf[i1];
            float2 w = tw[pos << (11 - sh)];
            float2 u = cmulf(bb, w);
            buf[i0] = make_float2(a.x + u.x, a.y + u.y);
            buf[i1] = make_float2(a.x - u.x, a.y - u.y);
        }
        __syncthreads();
    }
    for (int i = tid; i < 4096; i += 512) out[i] = buf[i];
}

// ---------------- Kernel 4: irfft(17->32) + softmax(32) + gate + residual + LayerNorm(256) ----------------
__global__ __launch_bounds__(256) void final_kernel(const float* __restrict__ v_in,
                                                    const float* __restrict__ gamma,
                                                    const float* __restrict__ beta,
                                                    float* __restrict__ out) {
    __shared__ float2 Zs[136][8];    // [h*17+j][nn]
    __shared__ float ct[32], st[32];
    __shared__ float red[16];

    const int tid = threadIdx.x;
    const int b = blockIdx.x >> 9;
    const int n0 = (blockIdx.x & 511) << 3;
    const int h = tid >> 5, d = tid & 31;

    if (tid < 32) {
        float s, c;
        sincospif((float)tid / 16.0f, &s, &c);   // 2*pi*tid/32
        ct[tid] = c; st[tid] = s;
    }
    // (b*8+hh)*17+j == b*136 + hj, so linear load:
    for (int e = tid; e < 136 * 8; e += 256) {
        int hj = e >> 3, nn = e & 7;
        Zs[hj][nn] = g_Z[((b * 136 + hj) << 12) + n0 + nn];
    }
    __syncthreads();

    const int hj0 = h * NBIN;
    for (int nn = 0; nn < 8; nn++) {
        // irfft over head_dim bins (Z[*,0] and Z[*,16] are numerically real)
        float cval = Zs[hj0][nn].x + ((d & 1) ? -Zs[hj0 + 16][nn].x : Zs[hj0 + 16][nn].x);
        int k = d;
#pragma unroll
        for (int j = 1; j <= 15; j++) {
            float2 z = Zs[hj0 + j][nn];
            cval = fmaf(2.0f * z.x, ct[k], cval);
            cval = fmaf(-2.0f * z.y, st[k], cval);
            k = (k + d) & 31;
        }
        cval *= (1.0f / 32.0f);

        // softmax over head_dim (warp == one head)
        float m = cval;
#pragma unroll
        for (int o = 16; o; o >>= 1) m = fmaxf(m, __shfl_xor_sync(0xffffffffu, m, o));
        float e = __expf(cval - m);
        float s = e;
#pragma unroll
        for (int o = 16; o; o >>= 1) s += __shfl_xor_sync(0xffffffffu, s, o);
        float p = e / s;

        const int row = (b * NSEQ + n0 + nn) * DIM + tid;
        float oval = fmaf(g_VL[row], p, v_in[row]);   // vl * attention + v (residual)

        // LayerNorm over 256 channels (block reduce)
        float s1 = oval, s2 = oval * oval;
#pragma unroll
        for (int o = 16; o; o >>= 1) {
            s1 += __shfl_xor_sync(0xffffffffu, s1, o);
            s2 += __shfl_xor_sync(0xffffffffu, s2, o);
        }
        if (d == 0) { red[h] = s1; red[8 + h] = s2; }
        __syncthreads();
        float S1 = 0.f, S2 = 0.f;
#pragma unroll
        for (int w = 0; w < 8; w++) { S1 += red[w]; S2 += red[8 + w]; }
        float mean = S1 * (1.0f / 256.0f);
        float var  = S2 * (1.0f / 256.0f) - mean * mean;
        float invs = rsqrtf(var + 1e-5f);
        out[row] = (oval - mean) * invs * gamma[tid] + beta[tid];
        __syncthreads();
    }
}

// ---------------- launch ----------------
extern "C" void kernel_launch(void* const* d_in, const int* in_sizes, int n_in,
                              void* d_out, int out_size) {
    const float* q  = (const float*)d_in[0];
    const float* k  = (const float*)d_in[1];
    const float* v  = (const float*)d_in[2];
    const float* Wq = (const float*)d_in[3];
    const float* bq = (const float*)d_in[4];
    const float* Wk = (const float*)d_in[5];
    const float* bk = (const float*)d_in[6];
    const float* Wv = (const float*)d_in[7];
    const float* bv = (const float*)d_in[8];
    const float* ln_gamma = (const float*)d_in[9];
    const float* ln_beta  = (const float*)d_in[10];
    float* out = (float*)d_out;

    GemmArgs ga;
    ga.X[0] = q;  ga.X[1] = k;  ga.X[2] = v;
    ga.W[0] = Wq; ga.W[1] = Wk; ga.W[2] = Wv;
    ga.bias[0] = bq; ga.bias[1] = bk; ga.bias[2] = bv;

    dim3 g1(MROWS / 128, DIM / 128, 3);
    proj_gemm<<<g1, 256>>>(ga);

    dim3 g2(BHN * (NSEQ / 128), 2);
    rfft_d_kernel<<<g2, 128>>>();

    fft_fwd_kernel<<<2 * BHN * NBIN, 512>>>();   // 2176 FFTs (Q + K)
    fft_inv_kernel<<<BHN * NBIN, 512>>>();       // 1088 product+inverse

    final_kernel<<<BB * (NSEQ / 8), 256>>>(v, ln_gamma, ln_beta, out);
}

// round 5
// speedup vs baseline: 1.5132x; 1.5132x over previous
#include <cuda_runtime.h>
#include <cstdint>

#define BB 8
#define NSEQ 4096
#define DIM 256
#define HEADS 8
#define HD 32
#define NBIN 17
#define MROWS (BB * NSEQ)        // 32768
#define BHN (BB * HEADS)         // 64
#define NXF (BHN * NBIN * NSEQ)  // 4456448 complex per array

// ---------------- scratch (static device memory; no allocations) ----------------
__device__ float  g_QL[MROWS * DIM];
__device__ float  g_KL[MROWS * DIM];
__device__ float  g_VL[MROWS * DIM];
__device__ float2 g_XF[2 * NXF];   // [0]=Qhat bins, [1]=Khat bins
__device__ float2 g_Z[NXF];        // seq-domain conv result (natural order)

__device__ __forceinline__ float2 cmulf(float2 a, float2 b) {
    return make_float2(fmaf(a.x, b.x, -a.y * b.y), fmaf(a.x, b.y, a.y * b.x));
}
__device__ __forceinline__ float2 caddf(float2 a, float2 b) { return make_float2(a.x + b.x, a.y + b.y); }
__device__ __forceinline__ float2 csubf(float2 a, float2 b) { return make_float2(a.x - b.x, a.y - b.y); }

// ======================= Kernel 1: 3xTF32 tensor-core projection GEMM =======================
// O[m,c] = sum_k X[m,k] * W[c,k] + bias[c], near-fp32 accuracy via hi/lo split.
struct GemmArgs {
    const float* X[3];
    const float* W[3];
    const float* bias[3];
};

__device__ __forceinline__ float to_tf32(float x) {
    float r;
    asm("cvt.rna.tf32.f32 %0, %1;" : "=f"(r) : "f"(x));
    return r;
}
__device__ __forceinline__ void split_tf32(float x, uint32_t& hi, uint32_t& lo) {
    float h = to_tf32(x);
    float l = to_tf32(x - h);
    hi = __float_as_uint(h);
    lo = __float_as_uint(l);
}
__device__ __forceinline__ void mma_tf32(float* c, const uint32_t* a, uint32_t b0, uint32_t b1) {
    asm volatile("mma.sync.aligned.m16n8k8.row.col.f32.tf32.tf32.f32 "
                 "{%0,%1,%2,%3}, {%4,%5,%6,%7}, {%8,%9}, {%0,%1,%2,%3};"
                 : "+f"(c[0]), "+f"(c[1]), "+f"(c[2]), "+f"(c[3])
                 : "r"(a[0]), "r"(a[1]), "r"(a[2]), "r"(a[3]), "r"(b0), "r"(b1));
}

#define SMP 136   // 128 + 8 padding: conflict-free frag loads

__global__ __launch_bounds__(256, 2) void proj_gemm_tf32(GemmArgs args) {
    __shared__ float As[2][16][SMP];
    __shared__ float Bs[2][16][SMP];

    const int z = blockIdx.z;
    const float* __restrict__ A    = args.X[z];
    const float* __restrict__ W    = args.W[z];
    const float* __restrict__ bias = args.bias[z];
    float* __restrict__ O = (z == 0) ? g_QL : (z == 1) ? g_KL : g_VL;

    const int bm = blockIdx.x * 128;
    const int bn = blockIdx.y * 128;
    const int tid  = threadIdx.x;
    const int warp = tid >> 5;
    const int lane = tid & 31;
    const int g  = lane >> 2;   // 0..7
    const int tq = lane & 3;    // 0..3
    const int wm = (warp & 3) * 32;
    const int wn = (warp >> 2) * 64;

    float acc[2][8][4];
#pragma unroll
    for (int s = 0; s < 2; s++)
#pragma unroll
        for (int nt = 0; nt < 8; nt++)
#pragma unroll
            for (int r = 0; r < 4; r++) acc[s][nt][r] = 0.f;

    float4 ra[2], rb[2];

    auto ldg_chunk = [&](int kk) {
#pragma unroll
        for (int q = 0; q < 2; q++) {
            int idx = tid + q * 256;
            int row = idx >> 2;
            int kc  = (idx & 3) << 2;
            ra[q] = *(const float4*)(A + (size_t)(bm + row) * DIM + kk * 16 + kc);
            rb[q] = *(const float4*)(W + (size_t)(bn + row) * DIM + kk * 16 + kc);
        }
    };
    auto sts_chunk = [&](int buf) {
#pragma unroll
        for (int q = 0; q < 2; q++) {
            int idx = tid + q * 256;
            int row = idx >> 2;
            int kc  = (idx & 3) << 2;
            As[buf][kc + 0][row] = ra[q].x;
            As[buf][kc + 1][row] = ra[q].y;
            As[buf][kc + 2][row] = ra[q].z;
            As[buf][kc + 3][row] = ra[q].w;
            Bs[buf][kc + 0][row] = rb[q].x;
            Bs[buf][kc + 1][row] = rb[q].y;
            Bs[buf][kc + 2][row] = rb[q].z;
            Bs[buf][kc + 3][row] = rb[q].w;
        }
    };

    ldg_chunk(0);
    sts_chunk(0);
    __syncthreads();

    for (int kk = 0; kk < 16; kk++) {
        const int cur = kk & 1;
        if (kk < 15) ldg_chunk(kk + 1);
#pragma unroll
        for (int ks = 0; ks < 2; ks++) {
            const int k0 = ks * 8;
            uint32_t afh[2][4], afl[2][4];
#pragma unroll
            for (int s = 0; s < 2; s++) {
                split_tf32(As[cur][k0 + tq][wm + 16 * s + g],         afh[s][0], afl[s][0]);
                split_tf32(As[cur][k0 + tq][wm + 16 * s + g + 8],     afh[s][1], afl[s][1]);
                split_tf32(As[cur][k0 + tq + 4][wm + 16 * s + g],     afh[s][2], afl[s][2]);
                split_tf32(As[cur][k0 + tq + 4][wm + 16 * s + g + 8], afh[s][3], afl[s][3]);
            }
#pragma unroll
            for (int nt = 0; nt < 8; nt++) {
                uint32_t b0h, b0l, b1h, b1l;
                split_tf32(Bs[cur][k0 + tq][wn + 8 * nt + g],     b0h, b0l);
                split_tf32(Bs[cur][k0 + tq + 4][wn + 8 * nt + g], b1h, b1l);
#pragma unroll
                for (int s = 0; s < 2; s++) {
                    mma_tf32(acc[s][nt], afh[s], b0h, b1h);   // hi*hi
                    mma_tf32(acc[s][nt], afh[s], b0l, b1l);   // hi*lo
                    mma_tf32(acc[s][nt], afl[s], b0h, b1h);   // lo*hi
                }
            }
        }
        if (kk < 15) {
            sts_chunk(1 - cur);
            __syncthreads();
        }
    }

    // epilogue
#pragma unroll
    for (int s = 0; s < 2; s++) {
        int row0 = bm + wm + 16 * s + g;
#pragma unroll
        for (int nt = 0; nt < 8; nt++) {
            int col = bn + wn + 8 * nt + 2 * tq;
            float b0 = bias[col], b1 = bias[col + 1];
            float2 v0 = make_float2(acc[s][nt][0] + b0, acc[s][nt][1] + b1);
            float2 v1 = make_float2(acc[s][nt][2] + b0, acc[s][nt][3] + b1);
            *(float2*)(O + (size_t)row0 * DIM + col)       = v0;
            *(float2*)(O + (size_t)(row0 + 8) * DIM + col) = v1;
        }
    }
}

// ======================= Kernel 2: rfft along head_dim (32 -> 17 bins) =======================
__global__ __launch_bounds__(128) void rfft_d_kernel() {
    __shared__ float xs[128][33];
    __shared__ float ct[32], st[32];
    const int y = blockIdx.y;
    const float* __restrict__ src = y ? g_KL : g_QL;
    float2* __restrict__ dst = g_XF + (size_t)y * NXF;

    const int bx = blockIdx.x;
    const int bh = bx >> 5;
    const int chunk = bx & 31;
    const int b = bh >> 3, h = bh & 7;
    const int n0 = chunk * 128;
    const int tid = threadIdx.x;

    if (tid < 32) {
        float s, c;
        sincospif((float)tid / 16.0f, &s, &c);
        ct[tid] = c; st[tid] = s;
    }
    const size_t rowbase = ((size_t)b * NSEQ + n0) * DIM + h * HD;
#pragma unroll
    for (int i = 0; i < 8; i++) {
        int idx = i * 128 + tid;
        int r = idx >> 3;
        int c = (idx & 7) << 2;
        float4 v = *(const float4*)(src + rowbase + (size_t)r * DIM + c);
        xs[r][c + 0] = v.x; xs[r][c + 1] = v.y; xs[r][c + 2] = v.z; xs[r][c + 3] = v.w;
    }
    __syncthreads();

    float x[32];
#pragma unroll
    for (int d = 0; d < 32; d++) x[d] = xs[tid][d];

    const int n = n0 + tid;
    for (int j = 0; j <= 16; j++) {
        float re = 0.f, im = 0.f;
        int k = 0;
#pragma unroll
        for (int d = 0; d < 32; d++) {
            re = fmaf(x[d], ct[k], re);
            im = fmaf(-x[d], st[k], im);
            k = (k + j) & 31;
        }
        dst[((size_t)(bh * NBIN + j) << 12) + n] = make_float2(re, im);
    }
}

// ======================= Kernel 3: fused radix-8 FFT conv =======================
#define SWZ(i) ((i) + ((i) >> 3))

template <bool INV>
__device__ __forceinline__ void dft8(const float2 x[8], float2 u[8]) {
    const float r2 = 0.70710678118654752f;
    float2 a0 = caddf(x[0], x[4]), b0 = csubf(x[0], x[4]);
    float2 a1 = caddf(x[1], x[5]), b1 = csubf(x[1], x[5]);
    float2 a2 = caddf(x[2], x[6]), b2 = csubf(x[2], x[6]);
    float2 a3 = caddf(x[3], x[7]), b3 = csubf(x[3], x[7]);
    float2 c0 = caddf(a0, a2), c2 = csubf(a0, a2);
    float2 c1 = caddf(a1, a3), c3 = csubf(a1, a3);
    u[0] = caddf(c0, c1); u[4] = csubf(c0, c1);
    if (!INV) {
        u[2] = make_float2(c2.x + c3.y, c2.y - c3.x);
        u[6] = make_float2(c2.x - c3.y, c2.y + c3.x);
    } else {
        u[2] = make_float2(c2.x - c3.y, c2.y + c3.x);
        u[6] = make_float2(c2.x + c3.y, c2.y - c3.x);
    }
    float2 d0 = b0, d1, d2, d3;
    if (!INV) {
        d1 = make_float2(r2 * (b1.x + b1.y), r2 * (b1.y - b1.x));
        d2 = make_float2(b2.y, -b2.x);
        d3 = make_float2(r2 * (b3.y - b3.x), r2 * (-b3.x - b3.y));
    } else {
        d1 = make_float2(r2 * (b1.x - b1.y), r2 * (b1.y + b1.x));
        d2 = make_float2(-b2.y, b2.x);
        d3 = make_float2(r2 * (-b3.x - b3.y), r2 * (b3.x - b3.y));
    }
    float2 e0 = caddf(d0, d2), e2 = csubf(d0, d2);
    float2 e1 = caddf(d1, d3), e3 = csubf(d1, d3);
    u[1] = caddf(e0, e1); u[5] = csubf(e0, e1);
    if (!INV) {
        u[3] = make_float2(e2.x + e3.y, e2.y - e3.x);
        u[7] = make_float2(e2.x - e3.y, e2.y + e3.x);
    } else {
        u[3] = make_float2(e2.x - e3.y, e2.y + e3.x);
        u[7] = make_float2(e2.x + e3.y, e2.y - e3.x);
    }
}

__device__ __forceinline__ float2 get_tw(int k, const float* twc, const float* tws, bool inv) {
    int k1 = k & 1023;
    int q  = (k >> 10) & 3;
    float c = twc[k1], s = tws[k1];
    float re = (q & 1) ? ((q & 2) ? s : -s) : ((q & 2) ? -c : c);
    float im = (q & 1) ? ((q & 2) ? c : -c) : ((q & 2) ? s : -s);
    return inv ? make_float2(re, -im) : make_float2(re, im);
}

template <int L, bool INV>
__device__ __forceinline__ void fft_stage(float* sre, float* sim,
                                          const float* twc, const float* tws, int t) {
    constexpr int LS   = L / 8;
    constexpr int TWST = 4096 / L;
    const int blk  = t / LS;
    const int j    = t & (LS - 1);
    const int base = blk * L + j;
    float2 x[8];
#pragma unroll
    for (int r = 0; r < 8; r++) {
        int i = SWZ(base + r * LS);
        x[r] = make_float2(sre[i], sim[i]);
    }
    float2 u[8];
    if (!INV) {
        dft8<false>(x, u);
#pragma unroll
        for (int r = 1; r < 8; r++)
            u[r] = cmulf(u[r], get_tw((j * r * TWST) & 4095, twc, tws, false));
    } else {
        float2 xt[8];
        xt[0] = x[0];
#pragma unroll
        for (int r = 1; r < 8; r++)
            xt[r] = cmulf(x[r], get_tw((j * r * TWST) & 4095, twc, tws, true));
        dft8<true>(xt, u);
    }
#pragma unroll
    for (int r = 0; r < 8; r++) {
        int i = SWZ(base + r * LS);
        sre[i] = u[r].x; sim[i] = u[r].y;
    }
}

__global__ __launch_bounds__(512) void fft_conv_kernel() {
    __shared__ float sre[4608], sim[4608];
    __shared__ float twc[1024], tws[1024];
    const int t = threadIdx.x;
    const size_t coff = (size_t)blockIdx.x << 12;
    const float2* __restrict__ qc = g_XF + coff;
    const float2* __restrict__ kc = g_XF + (size_t)NXF + coff;
    float2* __restrict__ outp = g_Z + coff;

    for (int k = t; k < 1024; k += 512) {
        float s, c;
        sincospif((float)k / 2048.0f, &s, &c);
        twc[k] = c; tws[k] = s;
    }
    // ---- forward Q ----
    for (int i = t; i < 4096; i += 512) {
        float2 v = qc[i];
        int s = SWZ(i);
        sre[s] = v.x; sim[s] = v.y;
    }
    __syncthreads();
    fft_stage<4096, false>(sre, sim, twc, tws, t); __syncthreads();
    fft_stage<512,  false>(sre, sim, twc, tws, t); __syncthreads();
    fft_stage<64,   false>(sre, sim, twc, tws, t); __syncthreads();
    float2 qf[8];
    {
        float2 x[8];
#pragma unroll
        for (int r = 0; r < 8; r++) {
            int i = SWZ(8 * t + r);
            x[r] = make_float2(sre[i], sim[i]);
        }
        dft8<false>(x, qf);
    }
    __syncthreads();
    // ---- forward K ----
    for (int i = t; i < 4096; i += 512) {
        float2 v = kc[i];
        int s = SWZ(i);
        sre[s] = v.x; sim[s] = v.y;
    }
    __syncthreads();
    fft_stage<4096, false>(sre, sim, twc, tws, t); __syncthreads();
    fft_stage<512,  false>(sre, sim, twc, tws, t); __syncthreads();
    fft_stage<64,   false>(sre, sim, twc, tws, t); __syncthreads();
    float2 kf[8];
    {
        float2 x[8];
#pragma unroll
        for (int r = 0; r < 8; r++) {
            int i = SWZ(8 * t + r);
            x[r] = make_float2(sre[i], sim[i]);
        }
        dft8<false>(x, kf);
    }
    // ---- product + inverse L=8 stage in registers ----
    {
        const float invN = 1.0f / 4096.0f;
        float2 p[8], u[8];
#pragma unroll
        for (int r = 0; r < 8; r++) {
            float2 m = cmulf(qf[r], kf[r]);
            p[r] = make_float2(m.x * invN, m.y * invN);
        }
        dft8<true>(p, u);
#pragma unroll
        for (int r = 0; r < 8; r++) {
            int i = SWZ(8 * t + r);
            sre[i] = u[r].x; sim[i] = u[r].y;
        }
    }
    __syncthreads();
    fft_stage<64,  true>(sre, sim, twc, tws, t); __syncthreads();
    fft_stage<512, true>(sre, sim, twc, tws, t); __syncthreads();
    // ---- inverse L=4096 stage, write natural order directly to GMEM ----
    {
        float2 x[8];
#pragma unroll
        for (int r = 0; r < 8; r++) {
            int i = SWZ(t + 512 * r);
            x[r] = make_float2(sre[i], sim[i]);
        }
        float2 xt[8];
        xt[0] = x[0];
#pragma unroll
        for (int r = 1; r < 8; r++)
            xt[r] = cmulf(x[r], get_tw((t * r) & 4095, twc, tws, true));
        float2 u[8];
        dft8<true>(xt, u);
#pragma unroll
        for (int r = 0; r < 8; r++) outp[t + 512 * r] = u[r];
    }
}

// ======================= Kernel 4: irfft + softmax + gate + residual + LayerNorm =======================
__global__ __launch_bounds__(256) void final_kernel(const float* __restrict__ v_in,
                                                    const float* __restrict__ gamma,
                                                    const float* __restrict__ beta,
                                                    float* __restrict__ out) {
    __shared__ float2 Zs[136][8];
    __shared__ float ct[32], st[32];
    __shared__ float red[16];

    const int tid = threadIdx.x;
    const int b = blockIdx.x >> 9;
    const int n0 = (blockIdx.x & 511) << 3;
    const int h = tid >> 5, d = tid & 31;

    if (tid < 32) {
        float s, c;
        sincospif((float)tid / 16.0f, &s, &c);
        ct[tid] = c; st[tid] = s;
    }
    for (int e = tid; e < 136 * 8; e += 256) {
        int hj = e >> 3, nn = e & 7;
        Zs[hj][nn] = g_Z[((size_t)(b * 136 + hj) << 12) + n0 + nn];
    }
    __syncthreads();

    const int hj0 = h * NBIN;
    for (int nn = 0; nn < 8; nn++) {
        float cval = Zs[hj0][nn].x + ((d & 1) ? -Zs[hj0 + 16][nn].x : Zs[hj0 + 16][nn].x);
        int k = d;
#pragma unroll
        for (int j = 1; j <= 15; j++) {
            float2 z = Zs[hj0 + j][nn];
            cval = fmaf(2.0f * z.x, ct[k], cval);
            cval = fmaf(-2.0f * z.y, st[k], cval);
            k = (k + d) & 31;
        }
        cval *= (1.0f / 32.0f);

        float m = cval;
#pragma unroll
        for (int o = 16; o; o >>= 1) m = fmaxf(m, __shfl_xor_sync(0xffffffffu, m, o));
        float e = __expf(cval - m);
        float s = e;
#pragma unroll
        for (int o = 16; o; o >>= 1) s += __shfl_xor_sync(0xffffffffu, s, o);
        float p = e / s;

        const size_t row = ((size_t)b * NSEQ + n0 + nn) * DIM + tid;
        float oval = fmaf(g_VL[row], p, v_in[row]);

        float s1 = oval, s2 = oval * oval;
#pragma unroll
        for (int o = 16; o; o >>= 1) {
            s1 += __shfl_xor_sync(0xffffffffu, s1, o);
            s2 += __shfl_xor_sync(0xffffffffu, s2, o);
        }
        if (d == 0) { red[h] = s1; red[8 + h] = s2; }
        __syncthreads();
        float S1 = 0.f, S2 = 0.f;
#pragma unroll
        for (int w = 0; w < 8; w++) { S1 += red[w]; S2 += red[8 + w]; }
        float mean = S1 * (1.0f / 256.0f);
        float var  = S2 * (1.0f / 256.0f) - mean * mean;
        float invs = rsqrtf(var + 1e-5f);
        out[row] = (oval - mean) * invs * gamma[tid] + beta[tid];
        __syncthreads();
    }
}

// ======================= launch =======================
extern "C" void kernel_launch(void* const* d_in, const int* in_sizes, int n_in,
                              void* d_out, int out_size) {
    const float* q  = (const float*)d_in[0];
    const float* k  = (const float*)d_in[1];
    const float* v  = (const float*)d_in[2];
    const float* Wq = (const float*)d_in[3];
    const float* bq = (const float*)d_in[4];
    const float* Wk = (const float*)d_in[5];
    const float* bk = (const float*)d_in[6];
    const float* Wv = (const float*)d_in[7];
    const float* bv = (const float*)d_in[8];
    const float* ln_gamma = (const float*)d_in[9];
    const float* ln_beta  = (const float*)d_in[10];
    float* out = (float*)d_out;

    GemmArgs ga;
    ga.X[0] = q;  ga.X[1] = k;  ga.X[2] = v;
    ga.W[0] = Wq; ga.W[1] = Wk; ga.W[2] = Wv;
    ga.bias[0] = bq; ga.bias[1] = bk; ga.bias[2] = bv;

    dim3 g1(MROWS / 128, DIM / 128, 3);
    proj_gemm_tf32<<<g1, 256>>>(ga);

    dim3 g2(BHN * (NSEQ / 128), 2);
    rfft_d_kernel<<<g2, 128>>>();

    fft_conv_kernel<<<BHN * NBIN, 512>>>();

    final_kernel<<<BB * (NSEQ / 8), 256>>>(v, ln_gamma, ln_beta, out);
}

// round 6
// speedup vs baseline: 1.5503x; 1.0245x over previous
#include <cuda_runtime.h>
#include <cstdint>

#define BB 8
#define NSEQ 4096
#define DIM 256
#define HEADS 8
#define HD 32
#define NBIN 17
#define MROWS (BB * NSEQ)        // 32768
#define BHN (BB * HEADS)         // 64
#define NXF (BHN * NBIN * NSEQ)  // 4456448 complex per array

// ---------------- scratch (static device memory; no allocations) ----------------
__device__ float  g_VL[MROWS * DIM];
__device__ float2 g_XF[2 * NXF];   // [0]=Qhat bins, [1]=Khat bins (natural seq order)
__device__ float2 g_Z[NXF];        // seq-domain conv result (natural order)

__device__ __forceinline__ float2 cmulf(float2 a, float2 b) {
    return make_float2(fmaf(a.x, b.x, -a.y * b.y), fmaf(a.x, b.y, a.y * b.x));
}
__device__ __forceinline__ float2 caddf(float2 a, float2 b) { return make_float2(a.x + b.x, a.y + b.y); }
__device__ __forceinline__ float2 csubf(float2 a, float2 b) { return make_float2(a.x - b.x, a.y - b.y); }

// ======================= Kernel 1: 3xTF32 GEMM + fused head-dim rfft epilogue =======================
// O[m,c] = sum_k X[m,k] * W[c,k] + bias[c].
// z=0 (Q), z=1 (K): epilogue computes 32->17-bin rfft per (row, head) and writes g_XF.
// z=2 (V): epilogue writes g_VL.
struct GemmArgs {
    const float* X[3];
    const float* W[3];
    const float* bias[3];
};

__device__ __forceinline__ float to_tf32(float x) {
    float r;
    asm("cvt.rna.tf32.f32 %0, %1;" : "=f"(r) : "f"(x));
    return r;
}
__device__ __forceinline__ void split_tf32(float x, uint32_t& hi, uint32_t& lo) {
    float h = to_tf32(x);
    float l = to_tf32(x - h);
    hi = __float_as_uint(h);
    lo = __float_as_uint(l);
}
__device__ __forceinline__ void mma_tf32(float* c, const uint32_t* a, uint32_t b0, uint32_t b1) {
    asm volatile("mma.sync.aligned.m16n8k8.row.col.f32.tf32.tf32.f32 "
                 "{%0,%1,%2,%3}, {%4,%5,%6,%7}, {%8,%9}, {%0,%1,%2,%3};"
                 : "+f"(c[0]), "+f"(c[1]), "+f"(c[2]), "+f"(c[3])
                 : "r"(a[0]), "r"(a[1]), "r"(a[2]), "r"(a[3]), "r"(b0), "r"(b1));
}

#define SMP 136   // 128 + 8 padding: conflict-free frag loads
#define TP  133   // epilogue tile pitch (gcd(133,32)=1 -> conflict-free column reads)

__global__ __launch_bounds__(256, 2) void proj_gemm_tf32(GemmArgs args) {
    __shared__ union SU {
        struct { float As[2][16][SMP]; float Bs[2][16][SMP]; } g;  // 34816 B
        float T[64][TP];                                            // 34048 B
    } su;
    __shared__ float ct[32], st[32];

    const int z = blockIdx.z;
    const float* __restrict__ A    = args.X[z];
    const float* __restrict__ W    = args.W[z];
    const float* __restrict__ bias = args.bias[z];

    const int bm = blockIdx.x * 128;
    const int bn = blockIdx.y * 128;
    const int tid  = threadIdx.x;
    const int warp = tid >> 5;
    const int lane = tid & 31;
    const int g  = lane >> 2;   // 0..7
    const int tq = lane & 3;    // 0..3
    const int wm = (warp & 3) * 32;
    const int wn = (warp >> 2) * 64;

    if (tid < 32) {
        float s, c;
        sincospif((float)tid / 16.0f, &s, &c);   // 2*pi*tid/32
        ct[tid] = c; st[tid] = s;
    }

    float acc[2][8][4];
#pragma unroll
    for (int s = 0; s < 2; s++)
#pragma unroll
        for (int nt = 0; nt < 8; nt++)
#pragma unroll
            for (int r = 0; r < 4; r++) acc[s][nt][r] = 0.f;

    float4 ra[2], rb[2];

    auto ldg_chunk = [&](int kk) {
#pragma unroll
        for (int q = 0; q < 2; q++) {
            int idx = tid + q * 256;
            int row = idx >> 2;
            int kc  = (idx & 3) << 2;
            ra[q] = *(const float4*)(A + (size_t)(bm + row) * DIM + kk * 16 + kc);
            rb[q] = *(const float4*)(W + (size_t)(bn + row) * DIM + kk * 16 + kc);
        }
    };
    auto sts_chunk = [&](int buf) {
#pragma unroll
        for (int q = 0; q < 2; q++) {
            int idx = tid + q * 256;
            int row = idx >> 2;
            int kc  = (idx & 3) << 2;
            su.g.As[buf][kc + 0][row] = ra[q].x;
            su.g.As[buf][kc + 1][row] = ra[q].y;
            su.g.As[buf][kc + 2][row] = ra[q].z;
            su.g.As[buf][kc + 3][row] = ra[q].w;
            su.g.Bs[buf][kc + 0][row] = rb[q].x;
            su.g.Bs[buf][kc + 1][row] = rb[q].y;
            su.g.Bs[buf][kc + 2][row] = rb[q].z;
            su.g.Bs[buf][kc + 3][row] = rb[q].w;
        }
    };

    ldg_chunk(0);
    sts_chunk(0);
    __syncthreads();

    for (int kk = 0; kk < 16; kk++) {
        const int cur = kk & 1;
        if (kk < 15) ldg_chunk(kk + 1);
#pragma unroll
        for (int ks = 0; ks < 2; ks++) {
            const int k0 = ks * 8;
            uint32_t afh[2][4], afl[2][4];
#pragma unroll
            for (int s = 0; s < 2; s++) {
                split_tf32(su.g.As[cur][k0 + tq][wm + 16 * s + g],         afh[s][0], afl[s][0]);
                split_tf32(su.g.As[cur][k0 + tq][wm + 16 * s + g + 8],     afh[s][1], afl[s][1]);
                split_tf32(su.g.As[cur][k0 + tq + 4][wm + 16 * s + g],     afh[s][2], afl[s][2]);
                split_tf32(su.g.As[cur][k0 + tq + 4][wm + 16 * s + g + 8], afh[s][3], afl[s][3]);
            }
#pragma unroll
            for (int nt = 0; nt < 8; nt++) {
                uint32_t b0h, b0l, b1h, b1l;
                split_tf32(su.g.Bs[cur][k0 + tq][wn + 8 * nt + g],     b0h, b0l);
                split_tf32(su.g.Bs[cur][k0 + tq + 4][wn + 8 * nt + g], b1h, b1l);
#pragma unroll
                for (int s = 0; s < 2; s++) {
                    mma_tf32(acc[s][nt], afh[s], b0h, b1h);   // hi*hi
                    mma_tf32(acc[s][nt], afh[s], b0l, b1l);   // hi*lo
                    mma_tf32(acc[s][nt], afl[s], b0h, b1h);   // lo*hi
                }
            }
        }
        if (kk < 15) {
            sts_chunk(1 - cur);
            __syncthreads();
        }
    }

    if (z == 2) {
        // plain epilogue -> g_VL
#pragma unroll
        for (int s = 0; s < 2; s++) {
            int row0 = bm + wm + 16 * s + g;
#pragma unroll
            for (int nt = 0; nt < 8; nt++) {
                int col = bn + wn + 8 * nt + 2 * tq;
                float b0 = bias[col], b1 = bias[col + 1];
                float2 v0 = make_float2(acc[s][nt][0] + b0, acc[s][nt][1] + b1);
                float2 v1 = make_float2(acc[s][nt][2] + b0, acc[s][nt][3] + b1);
                *(float2*)(g_VL + (size_t)row0 * DIM + col)       = v0;
                *(float2*)(g_VL + (size_t)(row0 + 8) * DIM + col) = v1;
            }
        }
        return;
    }

    // ---- fused rfft epilogue (z = 0 or 1) ----
    float2* __restrict__ XF = g_XF + (size_t)z * NXF;
    const int b      = bm >> 12;        // all 128 rows share batch
    const int nbase  = bm & 4095;
    const int hbase  = bn >> 5;         // 0 or 4

    for (int half = 0; half < 2; half++) {
        __syncthreads();   // As/Bs (pass 0) or previous T (pass 1) no longer needed
        if (((warp & 3) >> 1) == half) {
            const int rb0 = wm - half * 64;   // 0 or 32
#pragma unroll
            for (int s = 0; s < 2; s++) {
                int rr = rb0 + 16 * s + g;
#pragma unroll
                for (int nt = 0; nt < 8; nt++) {
                    int bcol = wn + 8 * nt + 2 * tq;
                    float b0 = bias[bn + bcol], b1 = bias[bn + bcol + 1];
                    su.T[rr][bcol]         = acc[s][nt][0] + b0;
                    su.T[rr][bcol + 1]     = acc[s][nt][1] + b1;
                    su.T[rr + 8][bcol]     = acc[s][nt][2] + b0;
                    su.T[rr + 8][bcol + 1] = acc[s][nt][3] + b1;
                }
            }
        }
        __syncthreads();

        const int h = tid >> 6;      // 0..3 (head within tile)
        const int r = tid & 63;      // 0..63 (row within half)
        float x[32];
#pragma unroll
        for (int d = 0; d < 32; d++) x[d] = su.T[r][h * 32 + d];

        const int n  = nbase + half * 64 + r;
        const int bh = b * 8 + hbase + h;
        for (int j = 0; j <= 16; j++) {
            float re = 0.f, im = 0.f;
            int k = 0;
#pragma unroll
            for (int d = 0; d < 32; d++) {
                re = fmaf(x[d], ct[k], re);
                im = fmaf(-x[d], st[k], im);
                k = (k + j) & 31;
            }
            XF[((size_t)(bh * NBIN + j) << 12) + n] = make_float2(re, im);
        }
    }
}

// ======================= Kernel 2: fused radix-8 FFT conv =======================
#define SWZ(i) ((i) + ((i) >> 3))

template <bool INV>
__device__ __forceinline__ void dft8(const float2 x[8], float2 u[8]) {
    const float r2 = 0.70710678118654752f;
    float2 a0 = caddf(x[0], x[4]), b0 = csubf(x[0], x[4]);
    float2 a1 = caddf(x[1], x[5]), b1 = csubf(x[1], x[5]);
    float2 a2 = caddf(x[2], x[6]), b2 = csubf(x[2], x[6]);
    float2 a3 = caddf(x[3], x[7]), b3 = csubf(x[3], x[7]);
    float2 c0 = caddf(a0, a2), c2 = csubf(a0, a2);
    float2 c1 = caddf(a1, a3), c3 = csubf(a1, a3);
    u[0] = caddf(c0, c1); u[4] = csubf(c0, c1);
    if (!INV) {
        u[2] = make_float2(c2.x + c3.y, c2.y - c3.x);
        u[6] = make_float2(c2.x - c3.y, c2.y + c3.x);
    } else {
        u[2] = make_float2(c2.x - c3.y, c2.y + c3.x);
        u[6] = make_float2(c2.x + c3.y, c2.y - c3.x);
    }
    float2 d0 = b0, d1, d2, d3;
    if (!INV) {
        d1 = make_float2(r2 * (b1.x + b1.y), r2 * (b1.y - b1.x));
        d2 = make_float2(b2.y, -b2.x);
        d3 = make_float2(r2 * (b3.y - b3.x), r2 * (-b3.x - b3.y));
    } else {
        d1 = make_float2(r2 * (b1.x - b1.y), r2 * (b1.y + b1.x));
        d2 = make_float2(-b2.y, b2.x);
        d3 = make_float2(r2 * (-b3.x - b3.y), r2 * (b3.x - b3.y));
    }
    float2 e0 = caddf(d0, d2), e2 = csubf(d0, d2);
    float2 e1 = caddf(d1, d3), e3 = csubf(d1, d3);
    u[1] = caddf(e0, e1); u[5] = csubf(e0, e1);
    if (!INV) {
        u[3] = make_float2(e2.x + e3.y, e2.y - e3.x);
        u[7] = make_float2(e2.x - e3.y, e2.y + e3.x);
    } else {
        u[3] = make_float2(e2.x - e3.y, e2.y + e3.x);
        u[7] = make_float2(e2.x + e3.y, e2.y - e3.x);
    }
}

__device__ __forceinline__ float2 get_tw(int k, const float* twc, const float* tws, bool inv) {
    int k1 = k & 1023;
    int q  = (k >> 10) & 3;
    float c = twc[k1], s = tws[k1];
    float re = (q & 1) ? ((q & 2) ? s : -s) : ((q & 2) ? -c : c);
    float im = (q & 1) ? ((q & 2) ? c : -c) : ((q & 2) ? s : -s);
    return inv ? make_float2(re, -im) : make_float2(re, im);
}

template <int L, bool INV>
__device__ __forceinline__ void fft_stage(float* sre, float* sim,
                                          const float* twc, const float* tws, int t) {
    constexpr int LS   = L / 8;
    constexpr int TWST = 4096 / L;
    const int blk  = t / LS;
    const int j    = t & (LS - 1);
    const int base = blk * L + j;
    float2 x[8];
#pragma unroll
    for (int r = 0; r < 8; r++) {
        int i = SWZ(base + r * LS);
        x[r] = make_float2(sre[i], sim[i]);
    }
    float2 u[8];
    if (!INV) {
        dft8<false>(x, u);
#pragma unroll
        for (int r = 1; r < 8; r++)
            u[r] = cmulf(u[r], get_tw((j * r * TWST) & 4095, twc, tws, false));
    } else {
        float2 xt[8];
        xt[0] = x[0];
#pragma unroll
        for (int r = 1; r < 8; r++)
            xt[r] = cmulf(x[r], get_tw((j * r * TWST) & 4095, twc, tws, true));
        dft8<true>(xt, u);
    }
#pragma unroll
    for (int r = 0; r < 8; r++) {
        int i = SWZ(base + r * LS);
        sre[i] = u[r].x; sim[i] = u[r].y;
    }
}

__global__ __launch_bounds__(512) void fft_conv_kernel() {
    __shared__ float sre[4608], sim[4608];
    __shared__ float twc[1024], tws[1024];
    const int t = threadIdx.x;
    const size_t coff = (size_t)blockIdx.x << 12;
    const float2* __restrict__ qc = g_XF + coff;
    const float2* __restrict__ kc = g_XF + (size_t)NXF + coff;
    float2* __restrict__ outp = g_Z + coff;

    for (int k = t; k < 1024; k += 512) {
        float s, c;
        sincospif((float)k / 2048.0f, &s, &c);
        twc[k] = c; tws[k] = s;
    }
    // ---- forward Q ----
    for (int i = t; i < 4096; i += 512) {
        float2 v = qc[i];
        int s = SWZ(i);
        sre[s] = v.x; sim[s] = v.y;
    }
    __syncthreads();
    fft_stage<4096, false>(sre, sim, twc, tws, t); __syncthreads();
    fft_stage<512,  false>(sre, sim, twc, tws, t); __syncthreads();
    fft_stage<64,   false>(sre, sim, twc, tws, t); __syncthreads();
    float2 qf[8];
    {
        float2 x[8];
#pragma unroll
        for (int r = 0; r < 8; r++) {
            int i = SWZ(8 * t + r);
            x[r] = make_float2(sre[i], sim[i]);
        }
        dft8<false>(x, qf);
    }
    __syncthreads();
    // ---- forward K ----
    for (int i = t; i < 4096; i += 512) {
        float2 v = kc[i];
        int s = SWZ(i);
        sre[s] = v.x; sim[s] = v.y;
    }
    __syncthreads();
    fft_stage<4096, false>(sre, sim, twc, tws, t); __syncthreads();
    fft_stage<512,  false>(sre, sim, twc, tws, t); __syncthreads();
    fft_stage<64,   false>(sre, sim, twc, tws, t); __syncthreads();
    float2 kf[8];
    {
        float2 x[8];
#pragma unroll
        for (int r = 0; r < 8; r++) {
            int i = SWZ(8 * t + r);
            x[r] = make_float2(sre[i], sim[i]);
        }
        dft8<false>(x, kf);
    }
    // ---- product + inverse L=8 stage in registers ----
    {
        const float invN = 1.0f / 4096.0f;
        float2 p[8], u[8];
#pragma unroll
        for (int r = 0; r < 8; r++) {
            float2 m = cmulf(qf[r], kf[r]);
            p[r] = make_float2(m.x * invN, m.y * invN);
        }
        dft8<true>(p, u);
#pragma unroll
        for (int r = 0; r < 8; r++) {
            int i = SWZ(8 * t + r);
            sre[i] = u[r].x; sim[i] = u[r].y;
        }
    }
    __syncthreads();
    fft_stage<64,  true>(sre, sim, twc, tws, t); __syncthreads();
    fft_stage<512, true>(sre, sim, twc, tws, t); __syncthreads();
    // ---- inverse L=4096 stage, write natural order directly to GMEM ----
    {
        float2 x[8];
#pragma unroll
        for (int r = 0; r < 8; r++) {
            int i = SWZ(t + 512 * r);
            x[r] = make_float2(sre[i], sim[i]);
        }
        float2 xt[8];
        xt[0] = x[0];
#pragma unroll
        for (int r = 1; r < 8; r++)
            xt[r] = cmulf(x[r], get_tw((t * r) & 4095, twc, tws, true));
        float2 u[8];
        dft8<true>(xt, u);
#pragma unroll
        for (int r = 0; r < 8; r++) outp[t + 512 * r] = u[r];
    }
}

// ======================= Kernel 3: irfft + softmax + gate + residual + LayerNorm =======================
// Warp-per-token: lane = d, 8 heads per lane. No block syncs in the hot path.
__global__ __launch_bounds__(256) void final_kernel(const float* __restrict__ v_in,
                                                    const float* __restrict__ gamma,
                                                    const float* __restrict__ beta,
                                                    float* __restrict__ out) {
    __shared__ float2 Zs[136][8];
    __shared__ float ct[32], st[32];
    __shared__ float sg[256], sb[256];

    const int tid = threadIdx.x;
    const int b = blockIdx.x >> 9;
    const int n0 = (blockIdx.x & 511) << 3;
    const int w = tid >> 5;      // warp = token slot
    const int d = tid & 31;      // lane = head-dim index

    if (tid < 32) {
        float s, c;
        sincospif((float)tid / 16.0f, &s, &c);
        ct[tid] = c; st[tid] = s;
    }
    sg[tid] = gamma[tid];
    sb[tid] = beta[tid];
    for (int e = tid; e < 136 * 8; e += 256) {
        int hj = e >> 3, nn = e & 7;
        Zs[hj][nn] = g_Z[((size_t)(b * 136 + hj) << 12) + n0 + nn];
    }
    __syncthreads();

    const int n = n0 + w;
    const size_t rowb = ((size_t)b * NSEQ + n) * DIM;

    float oval[8];
    float s1 = 0.f, s2 = 0.f;
#pragma unroll
    for (int h = 0; h < 8; h++) {
        const int hj0 = h * NBIN;
        float z16 = Zs[hj0 + 16][w].x;
        float cval = Zs[hj0][w].x + ((d & 1) ? -z16 : z16);
        int k = d;
#pragma unroll
        for (int j = 1; j <= 15; j++) {
            float2 z = Zs[hj0 + j][w];
            cval = fmaf(2.0f * z.x, ct[k], cval);
            cval = fmaf(-2.0f * z.y, st[k], cval);
            k = (k + d) & 31;
        }
        cval *= (1.0f / 32.0f);

        float m = cval;
#pragma unroll
        for (int o = 16; o; o >>= 1) m = fmaxf(m, __shfl_xor_sync(0xffffffffu, m, o));
        float e = __expf(cval - m);
        float ssum = e;
#pragma unroll
        for (int o = 16; o; o >>= 1) ssum += __shfl_xor_sync(0xffffffffu, ssum, o);
        float p = e / ssum;

        float vl = g_VL[rowb + h * 32 + d];
        float vv = v_in[rowb + h * 32 + d];
        float ov = fmaf(vl, p, vv);
        oval[h] = ov;
        s1 += ov;
        s2 = fmaf(ov, ov, s2);
    }
#pragma unroll
    for (int o = 16; o; o >>= 1) {
        s1 += __shfl_xor_sync(0xffffffffu, s1, o);
        s2 += __shfl_xor_sync(0xffffffffu, s2, o);
    }
    float mean = s1 * (1.0f / 256.0f);
    float var  = s2 * (1.0f / 256.0f) - mean * mean;
    float invs = rsqrtf(var + 1e-5f);
#pragma unroll
    for (int h = 0; h < 8; h++) {
        int c = h * 32 + d;
        out[rowb + c] = (oval[h] - mean) * invs * sg[c] + sb[c];
    }
}

// ======================= launch =======================
extern "C" void kernel_launch(void* const* d_in, const int* in_sizes, int n_in,
                              void* d_out, int out_size) {
    const float* q  = (const float*)d_in[0];
    const float* k  = (const float*)d_in[1];
    const float* v  = (const float*)d_in[2];
    const float* Wq = (const float*)d_in[3];
    const float* bq = (const float*)d_in[4];
    const float* Wk = (const float*)d_in[5];
    const float* bk = (const float*)d_in[6];
    const float* Wv = (const float*)d_in[7];
    const float* bv = (const float*)d_in[8];
    const float* ln_gamma = (const float*)d_in[9];
    const float* ln_beta  = (const float*)d_in[10];
    float* out = (float*)d_out;

    GemmArgs ga;
    ga.X[0] = q;  ga.X[1] = k;  ga.X[2] = v;
    ga.W[0] = Wq; ga.W[1] = Wk; ga.W[2] = Wv;
    ga.bias[0] = bq; ga.bias[1] = bk; ga.bias[2] = bv;

    dim3 g1(MROWS / 128, DIM / 128, 3);
    proj_gemm_tf32<<<g1, 256>>>(ga);

    fft_conv_kernel<<<BHN * NBIN, 512>>>();

    final_kernel<<<BB * (NSEQ / 8), 256>>>(v, ln_gamma, ln_beta, out);
}

// round 7
// speedup vs baseline: 1.8881x; 1.2179x over previous
#include <cuda_runtime.h>
#include <cuda_bf16.h>
#include <cstdint>

#define BB 8
#define NSEQ 4096
#define DIM 256
#define HEADS 8
#define HD 32
#define NBIN 17
#define MROWS (BB * NSEQ)        // 32768
#define BHN (BB * HEADS)         // 64
#define NXF (BHN * NBIN * NSEQ)  // 4456448 complex per array

// ---------------- scratch (static device memory; no allocations) ----------------
__device__ float  g_VL[MROWS * DIM];
__device__ float2 g_XF[2 * NXF];   // [0]=Qhat bins, [1]=Khat bins (natural seq order)
__device__ float2 g_Z[NXF];        // seq-domain conv result (natural order)

__device__ __forceinline__ float2 cmulf(float2 a, float2 b) {
    return make_float2(fmaf(a.x, b.x, -a.y * b.y), fmaf(a.x, b.y, a.y * b.x));
}
__device__ __forceinline__ float2 caddf(float2 a, float2 b) { return make_float2(a.x + b.x, a.y + b.y); }
__device__ __forceinline__ float2 csubf(float2 a, float2 b) { return make_float2(a.x - b.x, a.y - b.y); }

// ======================= Kernel 1: 3xBF16 GEMM + fused head-dim rfft epilogue =======================
// O[m,c] = sum_k X[m,k] * W[c,k] + bias[c].
// z=0 (Q), z=1 (K): epilogue computes 32->17-bin rfft per (row, head) and writes g_XF.
// z=2 (V): epilogue writes g_VL.
struct GemmArgs {
    const float* X[3];
    const float* W[3];
    const float* bias[3];
};

// pack (x_k, x_{k+1}) into bf16x2 hi plane + bf16x2 lo (residual) plane
__device__ __forceinline__ void split2_bf16(float x, float y, uint32_t& h, uint32_t& l) {
    __nv_bfloat162 hh = __floats2bfloat162_rn(x, y);        // .x = x (low half = even k)
    float rx = x - __bfloat162float(hh.x);
    float ry = y - __bfloat162float(hh.y);
    __nv_bfloat162 ll = __floats2bfloat162_rn(rx, ry);
    h = *reinterpret_cast<uint32_t*>(&hh);
    l = *reinterpret_cast<uint32_t*>(&ll);
}

__device__ __forceinline__ void mma_bf16(float* c, const uint32_t* a, uint32_t b0, uint32_t b1) {
    asm volatile("mma.sync.aligned.m16n8k16.row.col.f32.bf16.bf16.f32 "
                 "{%0,%1,%2,%3}, {%4,%5,%6,%7}, {%8,%9}, {%0,%1,%2,%3};"
                 : "+f"(c[0]), "+f"(c[1]), "+f"(c[2]), "+f"(c[3])
                 : "r"(a[0]), "r"(a[1]), "r"(a[2]), "r"(a[3]), "r"(b0), "r"(b1));
}

#define KP   20   // kpair pitch (words); 16 used. 20g+tq mod 32 distinct over g=0..7, tq=0..3
#define TP   133  // epilogue tile pitch (gcd(133,32)=1 -> conflict-free column reads)

__global__ __launch_bounds__(256, 2) void proj_gemm_bf16(GemmArgs args) {
    __shared__ union SU {
        struct {
            uint32_t Ah[128][KP];  // A hi pairs (bf16x2 along K)
            uint32_t Al[128][KP];
            uint32_t Bh[128][KP];
            uint32_t Bl[128][KP];
        } g;                       // 40960 B
        float T[64][TP];           // 34048 B
    } su;
    __shared__ float ct[32], st[32];

    const int z = blockIdx.z;
    const float* __restrict__ A    = args.X[z];
    const float* __restrict__ W    = args.W[z];
    const float* __restrict__ bias = args.bias[z];

    const int bm = blockIdx.x * 128;
    const int bn = blockIdx.y * 128;
    const int tid  = threadIdx.x;
    const int warp = tid >> 5;
    const int lane = tid & 31;
    const int g  = lane >> 2;   // 0..7
    const int tq = lane & 3;    // 0..3
    const int wm = (warp & 3) * 32;
    const int wn = (warp >> 2) * 64;

    if (tid < 32) {
        float s, c;
        sincospif((float)tid / 16.0f, &s, &c);   // 2*pi*tid/32
        ct[tid] = c; st[tid] = s;
    }

    float acc[2][8][4];
#pragma unroll
    for (int s = 0; s < 2; s++)
#pragma unroll
        for (int nt = 0; nt < 8; nt++)
#pragma unroll
            for (int r = 0; r < 4; r++) acc[s][nt][r] = 0.f;

    // staging: K-chunk = 32 floats; idx = tid + q*256 in [0,1024): row=idx>>3, kc=(idx&7)*4
    float4 ra[4], rb[4];

    auto ldg_chunk = [&](int kk) {
#pragma unroll
        for (int q = 0; q < 4; q++) {
            int idx = tid + q * 256;
            int row = idx >> 3;
            int kc  = (idx & 7) << 2;
            ra[q] = *(const float4*)(A + (size_t)(bm + row) * DIM + kk * 32 + kc);
            rb[q] = *(const float4*)(W + (size_t)(bn + row) * DIM + kk * 32 + kc);
        }
    };
    auto sts_chunk = [&]() {
#pragma unroll
        for (int q = 0; q < 4; q++) {
            int idx = tid + q * 256;
            int row = idx >> 3;
            int kp  = (idx & 7) << 1;   // kpair index 0,2,...,14
            uint32_t h0, l0, h1, l1;
            split2_bf16(ra[q].x, ra[q].y, h0, l0);
            split2_bf16(ra[q].z, ra[q].w, h1, l1);
            *(uint2*)&su.g.Ah[row][kp] = make_uint2(h0, h1);
            *(uint2*)&su.g.Al[row][kp] = make_uint2(l0, l1);
            split2_bf16(rb[q].x, rb[q].y, h0, l0);
            split2_bf16(rb[q].z, rb[q].w, h1, l1);
            *(uint2*)&su.g.Bh[row][kp] = make_uint2(h0, h1);
            *(uint2*)&su.g.Bl[row][kp] = make_uint2(l0, l1);
        }
    };

    ldg_chunk(0);
    for (int kk = 0; kk < 8; kk++) {
        __syncthreads();           // previous chunk fully consumed
        sts_chunk();
        __syncthreads();
        if (kk < 7) ldg_chunk(kk + 1);
#pragma unroll
        for (int ks = 0; ks < 2; ks++) {
            const int kb = ks * 8;   // kpair base (8 pairs = 16 K per mma step)
            uint32_t ah[2][4], al[2][4];
#pragma unroll
            for (int s = 0; s < 2; s++) {
                const int r0 = wm + 16 * s + g;
                ah[s][0] = su.g.Ah[r0][kb + tq];
                ah[s][1] = su.g.Ah[r0 + 8][kb + tq];
                ah[s][2] = su.g.Ah[r0][kb + tq + 4];
                ah[s][3] = su.g.Ah[r0 + 8][kb + tq + 4];
                al[s][0] = su.g.Al[r0][kb + tq];
                al[s][1] = su.g.Al[r0 + 8][kb + tq];
                al[s][2] = su.g.Al[r0][kb + tq + 4];
                al[s][3] = su.g.Al[r0 + 8][kb + tq + 4];
            }
#pragma unroll
            for (int nt = 0; nt < 8; nt++) {
                const int col = wn + 8 * nt + g;
                uint32_t bh0 = su.g.Bh[col][kb + tq];
                uint32_t bh1 = su.g.Bh[col][kb + tq + 4];
                uint32_t bl0 = su.g.Bl[col][kb + tq];
                uint32_t bl1 = su.g.Bl[col][kb + tq + 4];
#pragma unroll
                for (int s = 0; s < 2; s++) {
                    mma_bf16(acc[s][nt], ah[s], bh0, bh1);   // hi*hi
                    mma_bf16(acc[s][nt], ah[s], bl0, bl1);   // hi*lo
                    mma_bf16(acc[s][nt], al[s], bh0, bh1);   // lo*hi
                }
            }
        }
    }

    if (z == 2) {
        // plain epilogue -> g_VL  (C frag: c0,c1 = C[g][2tq,2tq+1]; c2,c3 = C[g+8][..])
#pragma unroll
        for (int s = 0; s < 2; s++) {
            int row0 = bm + wm + 16 * s + g;
#pragma unroll
            for (int nt = 0; nt < 8; nt++) {
                int col = bn + wn + 8 * nt + 2 * tq;
                float b0 = bias[col], b1 = bias[col + 1];
                float2 v0 = make_float2(acc[s][nt][0] + b0, acc[s][nt][1] + b1);
                float2 v1 = make_float2(acc[s][nt][2] + b0, acc[s][nt][3] + b1);
                *(float2*)(g_VL + (size_t)row0 * DIM + col)       = v0;
                *(float2*)(g_VL + (size_t)(row0 + 8) * DIM + col) = v1;
            }
        }
        return;
    }

    // ---- fused rfft epilogue (z = 0 or 1) ----
    float2* __restrict__ XF = g_XF + (size_t)z * NXF;
    const int b      = bm >> 12;        // all 128 rows share batch
    const int nbase  = bm & 4095;
    const int hbase  = bn >> 5;         // 0 or 4

    for (int half = 0; half < 2; half++) {
        __syncthreads();   // staging planes (pass 0) or previous T (pass 1) no longer needed
        if (((warp & 3) >> 1) == half) {
            const int rb0 = wm - half * 64;   // 0 or 32
#pragma unroll
            for (int s = 0; s < 2; s++) {
                int rr = rb0 + 16 * s + g;
#pragma unroll
                for (int nt = 0; nt < 8; nt++) {
                    int bcol = wn + 8 * nt + 2 * tq;
                    float b0 = bias[bn + bcol], b1 = bias[bn + bcol + 1];
                    su.T[rr][bcol]         = acc[s][nt][0] + b0;
                    su.T[rr][bcol + 1]     = acc[s][nt][1] + b1;
                    su.T[rr + 8][bcol]     = acc[s][nt][2] + b0;
                    su.T[rr + 8][bcol + 1] = acc[s][nt][3] + b1;
                }
            }
        }
        __syncthreads();

        const int h = tid >> 6;      // 0..3 (head within tile)
        const int r = tid & 63;      // 0..63 (row within half)
        float x[32];
#pragma unroll
        for (int d = 0; d < 32; d++) x[d] = su.T[r][h * 32 + d];

        const int n  = nbase + half * 64 + r;
        const int bh = b * 8 + hbase + h;
        for (int j = 0; j <= 16; j++) {
            float re = 0.f, im = 0.f;
            int k = 0;
#pragma unroll
            for (int d = 0; d < 32; d++) {
                re = fmaf(x[d], ct[k], re);
                im = fmaf(-x[d], st[k], im);
                k = (k + j) & 31;
            }
            XF[((size_t)(bh * NBIN + j) << 12) + n] = make_float2(re, im);
        }
    }
}

// ======================= Kernel 2: fused radix-8 FFT conv =======================
#define SWZ(i) ((i) + ((i) >> 3))

template <bool INV>
__device__ __forceinline__ void dft8(const float2 x[8], float2 u[8]) {
    const float r2 = 0.70710678118654752f;
    float2 a0 = caddf(x[0], x[4]), b0 = csubf(x[0], x[4]);
    float2 a1 = caddf(x[1], x[5]), b1 = csubf(x[1], x[5]);
    float2 a2 = caddf(x[2], x[6]), b2 = csubf(x[2], x[6]);
    float2 a3 = caddf(x[3], x[7]), b3 = csubf(x[3], x[7]);
    float2 c0 = caddf(a0, a2), c2 = csubf(a0, a2);
    float2 c1 = caddf(a1, a3), c3 = csubf(a1, a3);
    u[0] = caddf(c0, c1); u[4] = csubf(c0, c1);
    if (!INV) {
        u[2] = make_float2(c2.x + c3.y, c2.y - c3.x);
        u[6] = make_float2(c2.x - c3.y, c2.y + c3.x);
    } else {
        u[2] = make_float2(c2.x - c3.y, c2.y + c3.x);
        u[6] = make_float2(c2.x + c3.y, c2.y - c3.x);
    }
    float2 d0 = b0, d1, d2, d3;
    if (!INV) {
        d1 = make_float2(r2 * (b1.x + b1.y), r2 * (b1.y - b1.x));
        d2 = make_float2(b2.y, -b2.x);
        d3 = make_float2(r2 * (b3.y - b3.x), r2 * (-b3.x - b3.y));
    } else {
        d1 = make_float2(r2 * (b1.x - b1.y), r2 * (b1.y + b1.x));
        d2 = make_float2(-b2.y, b2.x);
        d3 = make_float2(r2 * (-b3.x - b3.y), r2 * (b3.x - b3.y));
    }
    float2 e0 = caddf(d0, d2), e2 = csubf(d0, d2);
    float2 e1 = caddf(d1, d3), e3 = csubf(d1, d3);
    u[1] = caddf(e0, e1); u[5] = csubf(e0, e1);
    if (!INV) {
        u[3] = make_float2(e2.x + e3.y, e2.y - e3.x);
        u[7] = make_float2(e2.x - e3.y, e2.y + e3.x);
    } else {
        u[3] = make_float2(e2.x - e3.y, e2.y + e3.x);
        u[7] = make_float2(e2.x + e3.y, e2.y - e3.x);
    }
}

__device__ __forceinline__ float2 get_tw(int k, const float* twc, const float* tws, bool inv) {
    int k1 = k & 1023;
    int q  = (k >> 10) & 3;
    float c = twc[k1], s = tws[k1];
    float re = (q & 1) ? ((q & 2) ? s : -s) : ((q & 2) ? -c : c);
    float im = (q & 1) ? ((q & 2) ? c : -c) : ((q & 2) ? s : -s);
    return inv ? make_float2(re, -im) : make_float2(re, im);
}

template <int L, bool INV>
__device__ __forceinline__ void fft_stage(float* sre, float* sim,
                                          const float* twc, const float* tws, int t) {
    constexpr int LS   = L / 8;
    constexpr int TWST = 4096 / L;
    const int blk  = t / LS;
    const int j    = t & (LS - 1);
    const int base = blk * L + j;
    float2 x[8];
#pragma unroll
    for (int r = 0; r < 8; r++) {
        int i = SWZ(base + r * LS);
        x[r] = make_float2(sre[i], sim[i]);
    }
    float2 u[8];
    if (!INV) {
        dft8<false>(x, u);
#pragma unroll
        for (int r = 1; r < 8; r++)
            u[r] = cmulf(u[r], get_tw((j * r * TWST) & 4095, twc, tws, false));
    } else {
        float2 xt[8];
        xt[0] = x[0];
#pragma unroll
        for (int r = 1; r < 8; r++)
            xt[r] = cmulf(x[r], get_tw((j * r * TWST) & 4095, twc, tws, true));
        dft8<true>(xt, u);
    }
#pragma unroll
    for (int r = 0; r < 8; r++) {
        int i = SWZ(base + r * LS);
        sre[i] = u[r].x; sim[i] = u[r].y;
    }
}

__global__ __launch_bounds__(512) void fft_conv_kernel() {
    __shared__ float sre[4608], sim[4608];
    __shared__ float twc[1024], tws[1024];
    const int t = threadIdx.x;
    const size_t coff = (size_t)blockIdx.x << 12;
    const float2* __restrict__ qc = g_XF + coff;
    const float2* __restrict__ kc = g_XF + (size_t)NXF + coff;
    float2* __restrict__ outp = g_Z + coff;

    for (int k = t; k < 1024; k += 512) {
        float s, c;
        sincospif((float)k / 2048.0f, &s, &c);
        twc[k] = c; tws[k] = s;
    }
    // ---- forward Q ----
    for (int i = t; i < 4096; i += 512) {
        float2 v = qc[i];
        int s = SWZ(i);
        sre[s] = v.x; sim[s] = v.y;
    }
    __syncthreads();
    fft_stage<4096, false>(sre, sim, twc, tws, t); __syncthreads();
    fft_stage<512,  false>(sre, sim, twc, tws, t); __syncthreads();
    fft_stage<64,   false>(sre, sim, twc, tws, t); __syncthreads();
    float2 qf[8];
    {
        float2 x[8];
#pragma unroll
        for (int r = 0; r < 8; r++) {
            int i = SWZ(8 * t + r);
            x[r] = make_float2(sre[i], sim[i]);
        }
        dft8<false>(x, qf);
    }
    __syncthreads();
    // ---- forward K ----
    for (int i = t; i < 4096; i += 512) {
        float2 v = kc[i];
        int s = SWZ(i);
        sre[s] = v.x; sim[s] = v.y;
    }
    __syncthreads();
    fft_stage<4096, false>(sre, sim, twc, tws, t); __syncthreads();
    fft_stage<512,  false>(sre, sim, twc, tws, t); __syncthreads();
    fft_stage<64,   false>(sre, sim, twc, tws, t); __syncthreads();
    float2 kf[8];
    {
        float2 x[8];
#pragma unroll
        for (int r = 0; r < 8; r++) {
            int i = SWZ(8 * t + r);
            x[r] = make_float2(sre[i], sim[i]);
        }
        dft8<false>(x, kf);
    }
    // ---- product + inverse L=8 stage in registers ----
    {
        const float invN = 1.0f / 4096.0f;
        float2 p[8], u[8];
#pragma unroll
        for (int r = 0; r < 8; r++) {
            float2 m = cmulf(qf[r], kf[r]);
            p[r] = make_float2(m.x * invN, m.y * invN);
        }
        dft8<true>(p, u);
#pragma unroll
        for (int r = 0; r < 8; r++) {
            int i = SWZ(8 * t + r);
            sre[i] = u[r].x; sim[i] = u[r].y;
        }
    }
    __syncthreads();
    fft_stage<64,  true>(sre, sim, twc, tws, t); __syncthreads();
    fft_stage<512, true>(sre, sim, twc, tws, t); __syncthreads();
    // ---- inverse L=4096 stage, write natural order directly to GMEM ----
    {
        float2 x[8];
#pragma unroll
        for (int r = 0; r < 8; r++) {
            int i = SWZ(t + 512 * r);
            x[r] = make_float2(sre[i], sim[i]);
        }
        float2 xt[8];
        xt[0] = x[0];
#pragma unroll
        for (int r = 1; r < 8; r++)
            xt[r] = cmulf(x[r], get_tw((t * r) & 4095, twc, tws, true));
        float2 u[8];
        dft8<true>(xt, u);
#pragma unroll
        for (int r = 0; r < 8; r++) outp[t + 512 * r] = u[r];
    }
}

// ======================= Kernel 3: irfft + softmax + gate + residual + LayerNorm =======================
// Warp-per-token: lane = d, 8 heads per lane. No block syncs in the hot path.
__global__ __launch_bounds__(256) void final_kernel(const float* __restrict__ v_in,
                                                    const float* __restrict__ gamma,
                                                    const float* __restrict__ beta,
                                                    float* __restrict__ out) {
    __shared__ float2 Zs[136][8];
    __shared__ float ct[32], st[32];
    __shared__ float sg[256], sb[256];

    const int tid = threadIdx.x;
    const int b = blockIdx.x >> 9;
    const int n0 = (blockIdx.x & 511) << 3;
    const int w = tid >> 5;      // warp = token slot
    const int d = tid & 31;      // lane = head-dim index

    if (tid < 32) {
        float s, c;
        sincospif((float)tid / 16.0f, &s, &c);
        ct[tid] = c; st[tid] = s;
    }
    sg[tid] = gamma[tid];
    sb[tid] = beta[tid];
    for (int e = tid; e < 136 * 8; e += 256) {
        int hj = e >> 3, nn = e & 7;
        Zs[hj][nn] = g_Z[((size_t)(b * 136 + hj) << 12) + n0 + nn];
    }
    __syncthreads();

    const int n = n0 + w;
    const size_t rowb = ((size_t)b * NSEQ + n) * DIM;

    float oval[8];
    float s1 = 0.f, s2 = 0.f;
#pragma unroll
    for (int h = 0; h < 8; h++) {
        const int hj0 = h * NBIN;
        float z16 = Zs[hj0 + 16][w].x;
        float cval = Zs[hj0][w].x + ((d & 1) ? -z16 : z16);
        int k = d;
#pragma unroll
        for (int j = 1; j <= 15; j++) {
            float2 z = Zs[hj0 + j][w];
            cval = fmaf(2.0f * z.x, ct[k], cval);
            cval = fmaf(-2.0f * z.y, st[k], cval);
            k = (k + d) & 31;
        }
        cval *= (1.0f / 32.0f);

        float m = cval;
#pragma unroll
        for (int o = 16; o; o >>= 1) m = fmaxf(m, __shfl_xor_sync(0xffffffffu, m, o));
        float e = __expf(cval - m);
        float ssum = e;
#pragma unroll
        for (int o = 16; o; o >>= 1) ssum += __shfl_xor_sync(0xffffffffu, ssum, o);
        float p = e / ssum;

        float vl = g_VL[rowb + h * 32 + d];
        float vv = v_in[rowb + h * 32 + d];
        float ov = fmaf(vl, p, vv);
        oval[h] = ov;
        s1 += ov;
        s2 = fmaf(ov, ov, s2);
    }
#pragma unroll
    for (int o = 16; o; o >>= 1) {
        s1 += __shfl_xor_sync(0xffffffffu, s1, o);
        s2 += __shfl_xor_sync(0xffffffffu, s2, o);
    }
    float mean = s1 * (1.0f / 256.0f);
    float var  = s2 * (1.0f / 256.0f) - mean * mean;
    float invs = rsqrtf(var + 1e-5f);
#pragma unroll
    for (int h = 0; h < 8; h++) {
        int c = h * 32 + d;
        out[rowb + c] = (oval[h] - mean) * invs * sg[c] + sb[c];
    }
}

// ======================= launch =======================
extern "C" void kernel_launch(void* const* d_in, const int* in_sizes, int n_in,
                              void* d_out, int out_size) {
    const float* q  = (const float*)d_in[0];
    const float* k  = (const float*)d_in[1];
    const float* v  = (const float*)d_in[2];
    const float* Wq = (const float*)d_in[3];
    const float* bq = (const float*)d_in[4];
    const float* Wk = (const float*)d_in[5];
    const float* bk = (const float*)d_in[6];
    const float* Wv = (const float*)d_in[7];
    const float* bv = (const float*)d_in[8];
    const float* ln_gamma = (const float*)d_in[9];
    const float* ln_beta  = (const float*)d_in[10];
    float* out = (float*)d_out;

    GemmArgs ga;
    ga.X[0] = q;  ga.X[1] = k;  ga.X[2] = v;
    ga.W[0] = Wq; ga.W[1] = Wk; ga.W[2] = Wv;
    ga.bias[0] = bq; ga.bias[1] = bk; ga.bias[2] = bv;

    dim3 g1(MROWS / 128, DIM / 128, 3);
    proj_gemm_bf16<<<g1, 256>>>(ga);

    fft_conv_kernel<<<BHN * NBIN, 512>>>();

    final_kernel<<<BB * (NSEQ / 8), 256>>>(v, ln_gamma, ln_beta, out);
}